// round 2
// baseline (speedup 1.0000x reference)
#include <cuda_runtime.h>
#include <math.h>

#define Sq   2048
#define DKd  64
#define TQ   16
#define KT1  256
#define PAD1 260
#define KT3  64
#define PAD3 68
#define NTHR 256
#define NBH  64   // B*H

// SMEM floats:
//   scores [TQ][Sq]     32768
//   q_s2   [64][32]      2048  (each q value duplicated: {q,q} pairs)
//   kv     [64][PAD1]   16640  (phase1 K transposed; phase3 reuses as V [64][PAD3])
//   pf     [TQ][64]      1024
//   pc     [TQ][64]      1024
//   inv    [TQ]            16
#define OFF_QS2 32768
#define OFF_KV  (OFF_QS2 + 2048)
#define OFF_PF  (OFF_KV + 64*PAD1)
#define OFF_PC  (OFF_PF + TQ*64)
#define OFF_INV (OFF_PC + TQ*64)
#define SMEM_FLOATS (OFF_INV + TQ)

typedef unsigned long long ull;

__device__ __forceinline__ ull fma2(ull a, ull b, ull c) {
    ull d;
    asm("fma.rn.f32x2 %0, %1, %2, %3;" : "=l"(d) : "l"(a), "l"(b), "l"(c));
    return d;
}
__device__ __forceinline__ ull pack2(float lo, float hi) {
    ull d;
    asm("mov.b64 %0, {%1, %2};" : "=l"(d) : "f"(lo), "f"(hi));
    return d;
}
__device__ __forceinline__ float2 unpack2(ull v) {
    float2 r;
    asm("mov.b64 {%0, %1}, %2;" : "=f"(r.x), "=f"(r.y) : "l"(v));
    return r;
}

__global__ __launch_bounds__(NTHR, 1)
void sdpa_kernel(const float* __restrict__ Q,
                 const float* __restrict__ K,
                 const float* __restrict__ V,
                 float* __restrict__ out_ctx,
                 float* __restrict__ out_attn)
{
    extern __shared__ float sm[];
    float* scores = sm;
    float* q_s2   = sm + OFF_QS2;
    float* kv     = sm + OFF_KV;
    float* pf     = sm + OFF_PF;
    float* pc     = sm + OFF_PC;
    float* inv    = sm + OFF_INV;

    const int t  = threadIdx.x;
    const int bh = blockIdx.y;
    const int q0 = blockIdx.x * TQ;

    const float* Qb = Q + (size_t)bh * Sq * DKd;
    const float* Kb = K + (size_t)bh * Sq * DKd;
    const float* Vb = V + (size_t)bh * Sq * DKd;

    // ---- load Q tile, duplicated pairs: q_s2[d*32 + 2q] = q_s2[d*32+2q+1] = Q[q][d]
    #pragma unroll
    for (int i = 0; i < 4; i++) {
        int idx = t + i * NTHR;
        int q = idx & 15, d = idx >> 4;
        float v = Qb[(size_t)(q0 + q) * DKd + d];
        q_s2[d * 32 + 2 * q]     = v;
        q_s2[d * 32 + 2 * q + 1] = v;
    }

    const int qg = t >> 6;   // 0..3 : queries qg*4 .. qg*4+3
    const int kg = t & 63;   // key group: keys kg*4 .. kg*4+3 within KT1 tile
    float sfull[4] = {0.f, 0.f, 0.f, 0.f};
    float scaus[4] = {0.f, 0.f, 0.f, 0.f};

    // ======== Phase 1: scores = exp(QK^T * scale); row sums ========
    for (int kt = 0; kt < Sq / KT1; kt++) {
        __syncthreads();
        // thread t loads K row (kt*256 + t), 64 floats, scatter transposed
        {
            const float4* krow = (const float4*)(Kb + (size_t)(kt * KT1 + t) * DKd);
            #pragma unroll
            for (int i = 0; i < 16; i++) {
                float4 f = krow[i];
                int d = 4 * i;
                kv[(d + 0) * PAD1 + t] = f.x;
                kv[(d + 1) * PAD1 + t] = f.y;
                kv[(d + 2) * PAD1 + t] = f.z;
                kv[(d + 3) * PAD1 + t] = f.w;
            }
        }
        __syncthreads();

        ull acc[4][2];
        #pragma unroll
        for (int i = 0; i < 4; i++) { acc[i][0] = 0ULL; acc[i][1] = 0ULL; }

        #pragma unroll 16
        for (int d = 0; d < DKd; d++) {
            const ull* qrow = (const ull*)(q_s2 + d * 32 + qg * 8);
            ull qp0 = qrow[0], qp1 = qrow[1], qp2 = qrow[2], qp3 = qrow[3];
            float4 k4 = *(const float4*)(kv + d * PAD1 + kg * 4);
            ull kp0 = pack2(k4.x, k4.y);
            ull kp1 = pack2(k4.z, k4.w);
            acc[0][0] = fma2(qp0, kp0, acc[0][0]); acc[0][1] = fma2(qp0, kp1, acc[0][1]);
            acc[1][0] = fma2(qp1, kp0, acc[1][0]); acc[1][1] = fma2(qp1, kp1, acc[1][1]);
            acc[2][0] = fma2(qp2, kp0, acc[2][0]); acc[2][1] = fma2(qp2, kp1, acc[2][1]);
            acc[3][0] = fma2(qp3, kp0, acc[3][0]); acc[3][1] = fma2(qp3, kp1, acc[3][1]);
        }

        int kbase = kt * KT1 + kg * 4;
        #pragma unroll
        for (int i = 0; i < 4; i++) {
            float2 s01 = unpack2(acc[i][0]);
            float2 s23 = unpack2(acc[i][1]);
            float4 ev;
            ev.x = __expf(s01.x * 0.125f);
            ev.y = __expf(s01.y * 0.125f);
            ev.z = __expf(s23.x * 0.125f);
            ev.w = __expf(s23.y * 0.125f);
            int qglob = q0 + qg * 4 + i;
            sfull[i] += (ev.x + ev.y) + (ev.z + ev.w);
            float c = 0.f;
            if (kbase     <= qglob) c += ev.x;
            if (kbase + 1 <= qglob) c += ev.y;
            if (kbase + 2 <= qglob) c += ev.z;
            if (kbase + 3 <= qglob) c += ev.w;
            scaus[i] += c;
            *(float4*)(scores + (qg * 4 + i) * Sq + kbase) = ev;
        }
    }

    // ======== Phase 1.5: reduce denominators ========
    #pragma unroll
    for (int i = 0; i < 4; i++) {
        pf[(qg * 4 + i) * 64 + kg] = sfull[i];
        pc[(qg * 4 + i) * 64 + kg] = scaus[i];
    }
    __syncthreads();
    if (t < TQ) {
        float sf = 0.f, sc = 0.f;
        #pragma unroll 8
        for (int j = 0; j < 64; j++) { sf += pf[t * 64 + j]; sc += pc[t * 64 + j]; }
        inv[t] = 1.0f / (sc + 1e-8f * sf);
    }
    __syncthreads();

    // ======== Phase 2: normalize + mask; write attn; store back (float4) ========
    {
        float4* attn4 = (float4*)(out_attn + ((size_t)bh * Sq + q0) * Sq);
        float4* sc4   = (float4*)scores;
        #pragma unroll 4
        for (int i4 = t; i4 < TQ * Sq / 4; i4 += NTHR) {
            int q  = i4 >> 9;              // (i4*4) / 2048
            int kb = (i4 & 511) * 4;
            float4 a = sc4[i4];
            float s  = inv[q];
            int qa   = q0 + q;
            a.x = (kb     <= qa) ? a.x * s : 0.0f;
            a.y = (kb + 1 <= qa) ? a.y * s : 0.0f;
            a.z = (kb + 2 <= qa) ? a.z * s : 0.0f;
            a.w = (kb + 3 <= qa) ? a.w * s : 0.0f;
            sc4[i4]   = a;
            attn4[i4] = a;
        }
    }

    // ======== Phase 3: context = attn @ V (causal tiles only), f32x2 ========
    const int dvg = (t >> 2) & 15;  // 16 dv-groups of 4
    const int ks  = t & 3;          // 4-way k slice, reduced via shfl
    ull c[4][2];
    #pragma unroll
    for (int i = 0; i < 4; i++) { c[i][0] = 0ULL; c[i][1] = 0ULL; }

    const int ntiles = q0 / KT3 + 1;
    for (int kt = 0; kt < ntiles; kt++) {
        __syncthreads();
        // load V tile [64][64] natural layout, pad PAD3
        #pragma unroll
        for (int i = 0; i < 4; i++) {
            int l = t + i * NTHR;           // 0..1023 float4s
            int k = l >> 4, dp = (l & 15) * 4;
            float4 f = *(const float4*)(Vb + (size_t)(kt * KT3 + k) * DKd + dp);
            *(float4*)(kv + k * PAD3 + dp) = f;
        }
        __syncthreads();

        const float* srow = scores + kt * KT3;
        #pragma unroll 4
        for (int kks = 0; kks < KT3; kks += 4) {
            int kk = kks + ks;
            float4 v4 = *(const float4*)(kv + kk * PAD3 + dvg * 4);
            ull vp0 = pack2(v4.x, v4.y);
            ull vp1 = pack2(v4.z, v4.w);
            #pragma unroll
            for (int i = 0; i < 4; i++) {
                float sv = srow[(qg * 4 + i) * Sq + kk];
                ull sp = pack2(sv, sv);
                c[i][0] = fma2(sp, vp0, c[i][0]);
                c[i][1] = fma2(sp, vp1, c[i][1]);
            }
        }
    }

    // reduce across the 4 k-slices (adjacent lanes) and write context
    #pragma unroll
    for (int i = 0; i < 4; i++) {
        float2 a = unpack2(c[i][0]);
        float2 b = unpack2(c[i][1]);
        float f0 = a.x, f1 = a.y, f2 = b.x, f3 = b.y;
        #pragma unroll
        for (int off = 1; off < 4; off <<= 1) {
            f0 += __shfl_xor_sync(0xffffffffu, f0, off);
            f1 += __shfl_xor_sync(0xffffffffu, f1, off);
            f2 += __shfl_xor_sync(0xffffffffu, f2, off);
            f3 += __shfl_xor_sync(0xffffffffu, f3, off);
        }
        if (ks == 0) {
            float4 o = make_float4(f0, f1, f2, f3);
            *(float4*)(out_ctx + ((size_t)bh * Sq + q0 + qg * 4 + i) * DKd + dvg * 4) = o;
        }
    }
}

extern "C" void kernel_launch(void* const* d_in, const int* in_sizes, int n_in,
                              void* d_out, int out_size)
{
    const float* Q = (const float*)d_in[0];
    const float* K = (const float*)d_in[1];
    const float* V = (const float*)d_in[2];
    float* ctx  = (float*)d_out;
    float* attn = (float*)d_out + (size_t)NBH * Sq * DKd;

    int smem_bytes = SMEM_FLOATS * (int)sizeof(float);
    cudaFuncSetAttribute(sdpa_kernel, cudaFuncAttributeMaxDynamicSharedMemorySize, smem_bytes);

    dim3 grid(Sq / TQ, NBH);
    sdpa_kernel<<<grid, NTHR, smem_bytes>>>(Q, K, V, ctx, attn);
    (void)in_sizes; (void)n_in; (void)out_size;
}

// round 4
// speedup vs baseline: 4.6797x; 4.6797x over previous
#include <cuda_runtime.h>
#include <cuda_bf16.h>
#include <cstdint>

#define Sq   2048
#define DKd  64
#define TQt  128
#define TKt  128
#define NTHR 512
#define NBH  64

#define SQK  72     // row stride (bf16 elems) for Q/K/V tiles
#define SP   136    // row stride (bf16 elems) for P tile

// smem byte offsets
#define OFF_QHI  0
#define OFF_QLO  18432
#define OFF_KHI  36864
#define OFF_KLO  55296
#define OFF_VHI  73728
#define OFF_VLO  92160
#define OFF_PHI  110592
#define OFF_PLO  145408
#define OFF_REDF 180224
#define OFF_REDC 182272
#define OFF_INV  184320
#define SMEM_BYTES (184832)

#define MMA(c, a, b) \
    asm volatile("mma.sync.aligned.m16n8k16.row.col.f32.bf16.bf16.f32 " \
        "{%0,%1,%2,%3}, {%4,%5,%6,%7}, {%8,%9}, {%0,%1,%2,%3};" \
        : "+f"((c)[0]), "+f"((c)[1]), "+f"((c)[2]), "+f"((c)[3]) \
        : "r"((a)[0]), "r"((a)[1]), "r"((a)[2]), "r"((a)[3]), \
          "r"((b)[0]), "r"((b)[1]))

__device__ __forceinline__ uint32_t smem_u32(const void* p) {
    uint32_t a;
    asm("{ .reg .u64 t; cvta.to.shared.u64 t, %1; cvt.u32.u64 %0, t; }" : "=r"(a) : "l"(p));
    return a;
}
__device__ __forceinline__ void ldmx2t(uint32_t& r0, uint32_t& r1, uint32_t addr) {
    asm volatile("ldmatrix.sync.aligned.m8n8.x2.trans.shared.b16 {%0,%1}, [%2];"
                 : "=r"(r0), "=r"(r1) : "r"(addr));
}
// pack (a,b) -> bf16x2 {lo=a, hi=b}, plus residual pair
__device__ __forceinline__ void split2(float a, float b, uint32_t& hi, uint32_t& lo) {
    asm("cvt.rn.bf16x2.f32 %0, %2, %1;" : "=r"(hi) : "f"(a), "f"(b));
    float ha = __uint_as_float(hi << 16);
    float hb = __uint_as_float(hi & 0xffff0000u);
    float la = a - ha, lb = b - hb;
    asm("cvt.rn.bf16x2.f32 %0, %2, %1;" : "=r"(lo) : "f"(la), "f"(lb));
}

// load 128x64 fp32 tile -> bf16 hi/lo smem (stride SQK)
__device__ __forceinline__ void load_split(const float* __restrict__ g, char* smc,
                                           int off_hi, int off_lo, int t) {
    #pragma unroll
    for (int i = 0; i < 4; i++) {
        int l = t + i * NTHR;         // 0..2047 float4
        int row = l >> 4, db = (l & 15) * 4;
        float4 f = *(const float4*)(g + (size_t)row * DKd + db);
        uint32_t h0, l0, h1, l1;
        split2(f.x, f.y, h0, l0);
        split2(f.z, f.w, h1, l1);
        int boff = (row * SQK + db) * 2;
        *(uint2*)(smc + off_hi + boff) = make_uint2(h0, h1);
        *(uint2*)(smc + off_lo + boff) = make_uint2(l0, l1);
    }
}

// S[32q x 32k] warp tile: 3-term bf16-split QK^T, fp32 accum
__device__ __forceinline__ void qk_tile(const char* smc, int mw, int nw, int g, int tg,
                                        float c[2][2][4]) {
    #pragma unroll
    for (int ks = 0; ks < 4; ks++) {
        int kc = ks * 16;
        uint32_t aH[2][4], aL[2][4];
        #pragma unroll
        for (int mi = 0; mi < 2; mi++) {
            int r0 = mw * 32 + mi * 16;
            int b0 = ((r0 + g) * SQK + kc + 2 * tg) * 2;
            int b1 = ((r0 + g + 8) * SQK + kc + 2 * tg) * 2;
            aH[mi][0] = *(const uint32_t*)(smc + OFF_QHI + b0);
            aH[mi][1] = *(const uint32_t*)(smc + OFF_QHI + b1);
            aH[mi][2] = *(const uint32_t*)(smc + OFF_QHI + b0 + 16);
            aH[mi][3] = *(const uint32_t*)(smc + OFF_QHI + b1 + 16);
            aL[mi][0] = *(const uint32_t*)(smc + OFF_QLO + b0);
            aL[mi][1] = *(const uint32_t*)(smc + OFF_QLO + b1);
            aL[mi][2] = *(const uint32_t*)(smc + OFF_QLO + b0 + 16);
            aL[mi][3] = *(const uint32_t*)(smc + OFF_QLO + b1 + 16);
        }
        uint32_t bH[4][2], bL[4][2];
        #pragma unroll
        for (int ni = 0; ni < 4; ni++) {
            int nr = nw * 32 + ni * 8 + g;
            int bb = (nr * SQK + kc + 2 * tg) * 2;
            bH[ni][0] = *(const uint32_t*)(smc + OFF_KHI + bb);
            bH[ni][1] = *(const uint32_t*)(smc + OFF_KHI + bb + 16);
            bL[ni][0] = *(const uint32_t*)(smc + OFF_KLO + bb);
            bL[ni][1] = *(const uint32_t*)(smc + OFF_KLO + bb + 16);
        }
        #pragma unroll
        for (int mi = 0; mi < 2; mi++)
            #pragma unroll
            for (int ni = 0; ni < 4; ni++) {
                MMA(c[mi][ni % 2 + 0], aH[mi], bH[ni]);  // placeholder avoided below
            }
        // NOTE: the above loop is replaced by explicit accumulation:
        (void)0;
    }
}

__global__ __launch_bounds__(NTHR, 1)
void sdpa_mma_kernel(const float* __restrict__ Q,
                     const float* __restrict__ K,
                     const float* __restrict__ V,
                     float* __restrict__ out_ctx,
                     float* __restrict__ out_attn)
{
    extern __shared__ char smc[];
    const uint32_t smb = smem_u32(smc);
    const int t    = threadIdx.x;
    const int wid  = t >> 5;
    const int lane = t & 31;
    const int g    = lane >> 2;
    const int tg   = lane & 3;
    const int mw   = wid >> 2;
    const int nw   = wid & 3;
    const int bh   = blockIdx.y;
    const int qt   = blockIdx.x;
    const int q0   = qt * TQt;

    const float* Qb = Q + (size_t)bh * Sq * DKd;
    const float* Kb = K + (size_t)bh * Sq * DKd;
    const float* Vb = V + (size_t)bh * Sq * DKd;
    float* attn_q = out_attn + ((size_t)bh * Sq + q0) * Sq;

    load_split(Qb + (size_t)q0 * DKd, smc, OFF_QHI, OFF_QLO, t);

    float sf[2][2] = {{0.f, 0.f}, {0.f, 0.f}};
    float sc[2][2] = {{0.f, 0.f}, {0.f, 0.f}};

    // ==================== PASS 1: denominators ====================
    for (int kt = 0; kt < Sq / TKt; kt++) {
        __syncthreads();
        load_split(Kb + (size_t)kt * TKt * DKd, smc, OFF_KHI, OFF_KLO, t);
        __syncthreads();

        float c[2][4][4];
        #pragma unroll
        for (int mi = 0; mi < 2; mi++)
            #pragma unroll
            for (int ni = 0; ni < 4; ni++)
                #pragma unroll
                for (int e = 0; e < 4; e++) c[mi][ni][e] = 0.f;

        #pragma unroll
        for (int ks = 0; ks < 4; ks++) {
            int kc = ks * 16;
            uint32_t aH[2][4], aL[2][4];
            #pragma unroll
            for (int mi = 0; mi < 2; mi++) {
                int r0 = mw * 32 + mi * 16;
                int b0 = ((r0 + g) * SQK + kc + 2 * tg) * 2;
                int b1 = ((r0 + g + 8) * SQK + kc + 2 * tg) * 2;
                aH[mi][0] = *(const uint32_t*)(smc + OFF_QHI + b0);
                aH[mi][1] = *(const uint32_t*)(smc + OFF_QHI + b1);
                aH[mi][2] = *(const uint32_t*)(smc + OFF_QHI + b0 + 16);
                aH[mi][3] = *(const uint32_t*)(smc + OFF_QHI + b1 + 16);
                aL[mi][0] = *(const uint32_t*)(smc + OFF_QLO + b0);
                aL[mi][1] = *(const uint32_t*)(smc + OFF_QLO + b1);
                aL[mi][2] = *(const uint32_t*)(smc + OFF_QLO + b0 + 16);
                aL[mi][3] = *(const uint32_t*)(smc + OFF_QLO + b1 + 16);
            }
            #pragma unroll
            for (int ni = 0; ni < 4; ni++) {
                int nr = nw * 32 + ni * 8 + g;
                int bb = (nr * SQK + kc + 2 * tg) * 2;
                uint32_t bH[2], bL[2];
                bH[0] = *(const uint32_t*)(smc + OFF_KHI + bb);
                bH[1] = *(const uint32_t*)(smc + OFF_KHI + bb + 16);
                bL[0] = *(const uint32_t*)(smc + OFF_KLO + bb);
                bL[1] = *(const uint32_t*)(smc + OFF_KLO + bb + 16);
                #pragma unroll
                for (int mi = 0; mi < 2; mi++) {
                    MMA(c[mi][ni], aH[mi], bH);
                    MMA(c[mi][ni], aH[mi], bL);
                    MMA(c[mi][ni], aL[mi], bH);
                }
            }
        }

        int cbase = kt * TKt + nw * 32;
        #pragma unroll
        for (int mi = 0; mi < 2; mi++) {
            int rg  = q0 + mw * 32 + mi * 16 + g;
            #pragma unroll
            for (int ni = 0; ni < 4; ni++) {
                int cl = cbase + ni * 8 + 2 * tg;
                float e0 = __expf(c[mi][ni][0] * 0.125f);
                float e1 = __expf(c[mi][ni][1] * 0.125f);
                float e2 = __expf(c[mi][ni][2] * 0.125f);
                float e3 = __expf(c[mi][ni][3] * 0.125f);
                sf[mi][0] += e0 + e1;
                sf[mi][1] += e2 + e3;
                if (cl     <= rg) sc[mi][0] += e0;
                if (cl + 1 <= rg) sc[mi][0] += e1;
                if (cl     <= rg + 8) sc[mi][1] += e2;
                if (cl + 1 <= rg + 8) sc[mi][1] += e3;
            }
        }
    }

    // reduce across tg lanes, then across nw warps via smem
    {
        float* redf = (float*)(smc + OFF_REDF);
        float* redc = (float*)(smc + OFF_REDC);
        #pragma unroll
        for (int mi = 0; mi < 2; mi++)
            #pragma unroll
            for (int rr = 0; rr < 2; rr++) {
                float vf = sf[mi][rr], vc = sc[mi][rr];
                vf += __shfl_xor_sync(0xffffffffu, vf, 1);
                vf += __shfl_xor_sync(0xffffffffu, vf, 2);
                vc += __shfl_xor_sync(0xffffffffu, vc, 1);
                vc += __shfl_xor_sync(0xffffffffu, vc, 2);
                if (tg == 0) {
                    int row = mw * 32 + mi * 16 + rr * 8 + g;
                    redf[row * 4 + nw] = vf;
                    redc[row * 4 + nw] = vc;
                }
            }
    }
    __syncthreads();
    if (t < 128) {
        const float* rf = (const float*)(smc + OFF_REDF) + t * 4;
        const float* rc = (const float*)(smc + OFF_REDC) + t * 4;
        float vf = (rf[0] + rf[1]) + (rf[2] + rf[3]);
        float vc = (rc[0] + rc[1]) + (rc[2] + rc[3]);
        ((float*)(smc + OFF_INV))[t] = 1.0f / (vc + 1e-8f * vf);
    }
    // zero-fill attn above diagonal tiles
    {
        int zc0 = (qt + 1) * TKt;
        int zf4 = (Sq - zc0) >> 2;
        if (zf4 > 0) {
            float4 z = make_float4(0.f, 0.f, 0.f, 0.f);
            for (int idx = t; idx < TQt * zf4; idx += NTHR) {
                int rr = idx / zf4, c4 = idx - rr * zf4;
                *(float4*)(attn_q + (size_t)rr * Sq + zc0 + c4 * 4) = z;
            }
        }
    }
    __syncthreads();

    float invr[2][2];
    #pragma unroll
    for (int mi = 0; mi < 2; mi++) {
        invr[mi][0] = ((const float*)(smc + OFF_INV))[mw * 32 + mi * 16 + g];
        invr[mi][1] = ((const float*)(smc + OFF_INV))[mw * 32 + mi * 16 + g + 8];
    }

    // ==================== PASS 2: attn + context ====================
    float av[2][2][4];
    #pragma unroll
    for (int mi = 0; mi < 2; mi++)
        #pragma unroll
        for (int ni = 0; ni < 2; ni++)
            #pragma unroll
            for (int e = 0; e < 4; e++) av[mi][ni][e] = 0.f;

    for (int kt = 0; kt <= qt; kt++) {
        __syncthreads();
        load_split(Kb + (size_t)kt * TKt * DKd, smc, OFF_KHI, OFF_KLO, t);
        load_split(Vb + (size_t)kt * TKt * DKd, smc, OFF_VHI, OFF_VLO, t);
        __syncthreads();

        float c[2][4][4];
        #pragma unroll
        for (int mi = 0; mi < 2; mi++)
            #pragma unroll
            for (int ni = 0; ni < 4; ni++)
                #pragma unroll
                for (int e = 0; e < 4; e++) c[mi][ni][e] = 0.f;

        #pragma unroll
        for (int ks = 0; ks < 4; ks++) {
            int kc = ks * 16;
            uint32_t aH[2][4], aL[2][4];
            #pragma unroll
            for (int mi = 0; mi < 2; mi++) {
                int r0 = mw * 32 + mi * 16;
                int b0 = ((r0 + g) * SQK + kc + 2 * tg) * 2;
                int b1 = ((r0 + g + 8) * SQK + kc + 2 * tg) * 2;
                aH[mi][0] = *(const uint32_t*)(smc + OFF_QHI + b0);
                aH[mi][1] = *(const uint32_t*)(smc + OFF_QHI + b1);
                aH[mi][2] = *(const uint32_t*)(smc + OFF_QHI + b0 + 16);
                aH[mi][3] = *(const uint32_t*)(smc + OFF_QHI + b1 + 16);
                aL[mi][0] = *(const uint32_t*)(smc + OFF_QLO + b0);
                aL[mi][1] = *(const uint32_t*)(smc + OFF_QLO + b1);
                aL[mi][2] = *(const uint32_t*)(smc + OFF_QLO + b0 + 16);
                aL[mi][3] = *(const uint32_t*)(smc + OFF_QLO + b1 + 16);
            }
            #pragma unroll
            for (int ni = 0; ni < 4; ni++) {
                int nr = nw * 32 + ni * 8 + g;
                int bb = (nr * SQK + kc + 2 * tg) * 2;
                uint32_t bH[2], bL[2];
                bH[0] = *(const uint32_t*)(smc + OFF_KHI + bb);
                bH[1] = *(const uint32_t*)(smc + OFF_KHI + bb + 16);
                bL[0] = *(const uint32_t*)(smc + OFF_KLO + bb);
                bL[1] = *(const uint32_t*)(smc + OFF_KLO + bb + 16);
                #pragma unroll
                for (int mi = 0; mi < 2; mi++) {
                    MMA(c[mi][ni], aH[mi], bH);
                    MMA(c[mi][ni], aH[mi], bL);
                    MMA(c[mi][ni], aL[mi], bH);
                }
            }
        }

        // P = exp * inv * mask -> attn gmem (fp32) + smem (bf16 split)
        #pragma unroll
        for (int mi = 0; mi < 2; mi++) {
            int rloc0 = mw * 32 + mi * 16 + g;
            int rg  = q0 + rloc0;
            #pragma unroll
            for (int ni = 0; ni < 4; ni++) {
                int cl = nw * 32 + ni * 8 + 2 * tg;
                int cg = kt * TKt + cl;
                float p0 = __expf(c[mi][ni][0] * 0.125f) * invr[mi][0];
                float p1 = __expf(c[mi][ni][1] * 0.125f) * invr[mi][0];
                float p2 = __expf(c[mi][ni][2] * 0.125f) * invr[mi][1];
                float p3 = __expf(c[mi][ni][3] * 0.125f) * invr[mi][1];
                p0 = (cg     <= rg) ? p0 : 0.f;
                p1 = (cg + 1 <= rg) ? p1 : 0.f;
                p2 = (cg     <= rg + 8) ? p2 : 0.f;
                p3 = (cg + 1 <= rg + 8) ? p3 : 0.f;
                *(float2*)(attn_q + (size_t)rloc0 * Sq + cg) = make_float2(p0, p1);
                *(float2*)(attn_q + (size_t)(rloc0 + 8) * Sq + cg) = make_float2(p2, p3);
                uint32_t hi, lo;
                split2(p0, p1, hi, lo);
                int bo = (rloc0 * SP + cl) * 2;
                *(uint32_t*)(smc + OFF_PHI + bo) = hi;
                *(uint32_t*)(smc + OFF_PLO + bo) = lo;
                split2(p2, p3, hi, lo);
                bo = ((rloc0 + 8) * SP + cl) * 2;
                *(uint32_t*)(smc + OFF_PHI + bo) = hi;
                *(uint32_t*)(smc + OFF_PLO + bo) = lo;
            }
        }
        __syncthreads();

        // context += P @ V  (warp: 32q x 16dv)
        #pragma unroll
        for (int ks = 0; ks < 8; ks++) {
            int kc = ks * 16;
            uint32_t aH[2][4], aL[2][4];
            #pragma unroll
            for (int mi = 0; mi < 2; mi++) {
                int r0 = mw * 32 + mi * 16;
                int b0 = ((r0 + g) * SP + kc + 2 * tg) * 2;
                int b1 = ((r0 + g + 8) * SP + kc + 2 * tg) * 2;
                aH[mi][0] = *(const uint32_t*)(smc + OFF_PHI + b0);
                aH[mi][1] = *(const uint32_t*)(smc + OFF_PHI + b1);
                aH[mi][2] = *(const uint32_t*)(smc + OFF_PHI + b0 + 16);
                aH[mi][3] = *(const uint32_t*)(smc + OFF_PHI + b1 + 16);
                aL[mi][0] = *(const uint32_t*)(smc + OFF_PLO + b0);
                aL[mi][1] = *(const uint32_t*)(smc + OFF_PLO + b1);
                aL[mi][2] = *(const uint32_t*)(smc + OFF_PLO + b0 + 16);
                aL[mi][3] = *(const uint32_t*)(smc + OFF_PLO + b1 + 16);
            }
            #pragma unroll
            for (int ni = 0; ni < 2; ni++) {
                uint32_t vrow = (uint32_t)(kc + (lane & 15));
                uint32_t coff = (uint32_t)((nw * 16 + ni * 8) * 2);
                uint32_t bH[2], bL[2];
                ldmx2t(bH[0], bH[1], smb + OFF_VHI + vrow * (SQK * 2) + coff);
                ldmx2t(bL[0], bL[1], smb + OFF_VLO + vrow * (SQK * 2) + coff);
                #pragma unroll
                for (int mi = 0; mi < 2; mi++) {
                    MMA(av[mi][ni], aH[mi], bH);
                    MMA(av[mi][ni], aH[mi], bL);
                    MMA(av[mi][ni], aL[mi], bH);
                }
            }
        }
    }

    // ==================== context output ====================
    #pragma unroll
    for (int mi = 0; mi < 2; mi++) {
        int rloc0 = mw * 32 + mi * 16 + g;
        #pragma unroll
        for (int ni = 0; ni < 2; ni++) {
            int cl = nw * 16 + ni * 8 + 2 * tg;
            *(float2*)(out_ctx + ((size_t)bh * Sq + q0 + rloc0) * DKd + cl) =
                make_float2(av[mi][ni][0], av[mi][ni][1]);
            *(float2*)(out_ctx + ((size_t)bh * Sq + q0 + rloc0 + 8) * DKd + cl) =
                make_float2(av[mi][ni][2], av[mi][ni][3]);
        }
    }
}

extern "C" void kernel_launch(void* const* d_in, const int* in_sizes, int n_in,
                              void* d_out, int out_size)
{
    const float* Q = (const float*)d_in[0];
    const float* K = (const float*)d_in[1];
    const float* V = (const float*)d_in[2];
    float* ctx  = (float*)d_out;
    float* attn = (float*)d_out + (size_t)NBH * Sq * DKd;

    cudaFuncSetAttribute(sdpa_mma_kernel, cudaFuncAttributeMaxDynamicSharedMemorySize, SMEM_BYTES);
    dim3 grid(Sq / TQt, NBH);
    sdpa_mma_kernel<<<grid, NTHR, SMEM_BYTES>>>(Q, K, V, ctx, attn);
    (void)in_sizes; (void)n_in; (void)out_size;
}

// round 5
// speedup vs baseline: 5.6181x; 1.2005x over previous
#include <cuda_runtime.h>
#include <cuda_fp16.h>
#include <cstdint>

#define Sq   2048
#define DKd  64
#define TQt  128
#define NTHR 512
#define NBH  64

#define SB   144    // Q/K/V row stride in bytes (72 fp16)
#define SPB  272    // P row stride in bytes (136 fp16)

// smem byte offsets
#define OFF_QHI  0
#define OFF_QLO  18432
#define OFF_KHI  36864
#define OFF_KLO  55296
#define OFF_VHI  73728
#define OFF_VLO  92160
#define OFF_P    110592
#define OFF_REDF 145408
#define OFF_REDC 147456
#define OFF_INV  149504
#define SMEM_BYTES 150016

#define MMAH(c, a, b) \
    asm volatile("mma.sync.aligned.m16n8k16.row.col.f32.f16.f16.f32 " \
        "{%0,%1,%2,%3}, {%4,%5,%6,%7}, {%8,%9}, {%0,%1,%2,%3};" \
        : "+f"((c)[0]), "+f"((c)[1]), "+f"((c)[2]), "+f"((c)[3]) \
        : "r"((a)[0]), "r"((a)[1]), "r"((a)[2]), "r"((a)[3]), \
          "r"((b)[0]), "r"((b)[1]))

__device__ __forceinline__ uint32_t smem_u32(const void* p) {
    uint32_t a;
    asm("{ .reg .u64 t; cvta.to.shared.u64 t, %1; cvt.u32.u64 %0, t; }" : "=r"(a) : "l"(p));
    return a;
}
__device__ __forceinline__ void ldm4(uint32_t r[4], uint32_t addr) {
    asm volatile("ldmatrix.sync.aligned.m8n8.x4.shared.b16 {%0,%1,%2,%3}, [%4];"
                 : "=r"(r[0]), "=r"(r[1]), "=r"(r[2]), "=r"(r[3]) : "r"(addr));
}
__device__ __forceinline__ void ldm2t(uint32_t& r0, uint32_t& r1, uint32_t addr) {
    asm volatile("ldmatrix.sync.aligned.m8n8.x2.trans.shared.b16 {%0,%1}, [%2];"
                 : "=r"(r0), "=r"(r1) : "r"(addr));
}
// (a,b) -> fp16x2 hi, fp16x2 residual lo
__device__ __forceinline__ void split2h(float a, float b, uint32_t& hi, uint32_t& lo) {
    __half2 h = __floats2half2_rn(a, b);
    hi = *(uint32_t*)&h;
    float2 hf = __half22float2(h);
    __half2 l = __floats2half2_rn(a - hf.x, b - hf.y);
    lo = *(uint32_t*)&l;
}
__device__ __forceinline__ uint32_t packh(float a, float b) {
    __half2 h = __floats2half2_rn(a, b);
    return *(uint32_t*)&h;
}

// thread t owns row t>>2, cols (t&3)*16 .. +15 of a 128x64 fp32 tile
__device__ __forceinline__ void ldg_tile(const float* __restrict__ g, int t, float4 f[4]) {
    const float4* p = (const float4*)(g + (size_t)(t >> 2) * DKd + (t & 3) * 16);
    f[0] = p[0]; f[1] = p[1]; f[2] = p[2]; f[3] = p[3];
}
__device__ __forceinline__ void sts_split(char* smc, int off_hi, int off_lo, int t,
                                          const float4 f[4], bool lo_too) {
    uint32_t h[8], l[8];
    #pragma unroll
    for (int j = 0; j < 4; j++) {
        split2h(f[j].x, f[j].y, h[2 * j], l[2 * j]);
        split2h(f[j].z, f[j].w, h[2 * j + 1], l[2 * j + 1]);
    }
    int b = (t >> 2) * SB + (t & 3) * 32;
    *(uint4*)(smc + off_hi + b)      = make_uint4(h[0], h[1], h[2], h[3]);
    *(uint4*)(smc + off_hi + b + 16) = make_uint4(h[4], h[5], h[6], h[7]);
    if (lo_too) {
        *(uint4*)(smc + off_lo + b)      = make_uint4(l[0], l[1], l[2], l[3]);
        *(uint4*)(smc + off_lo + b + 16) = make_uint4(l[4], l[5], l[6], l[7]);
    }
}

__global__ __launch_bounds__(NTHR, 1)
void sdpa_mma_kernel(const float* __restrict__ Q,
                     const float* __restrict__ K,
                     const float* __restrict__ V,
                     float* __restrict__ out_ctx,
                     float* __restrict__ out_attn)
{
    extern __shared__ char smc[];
    const uint32_t smb = smem_u32(smc);
    const int t    = threadIdx.x;
    const int wid  = t >> 5;
    const int lane = t & 31;
    const int g    = lane >> 2;
    const int tg   = lane & 3;
    const int mw   = wid >> 2;
    const int nw   = wid & 3;
    const int bh   = blockIdx.y;
    const int qt   = blockIdx.x;
    const int q0   = qt * TQt;

    // per-lane ldmatrix address offsets
    const int aRow = (lane & 7) + ((lane >> 3) & 1) * 8;   // A (x4)
    const int aCol = (lane >> 4) * 8;
    const int bRow = (lane & 7) + (lane >> 4) * 8;          // B (x4)
    const int bCol = ((lane >> 3) & 1) * 8;
    const int vRow = lane & 15;                              // V (x2 trans)

    const float* Qb = Q + (size_t)bh * Sq * DKd;
    const float* Kb = K + (size_t)bh * Sq * DKd;
    const float* Vb = V + (size_t)bh * Sq * DKd;
    float* attn_q = out_attn + ((size_t)bh * Sq + q0) * Sq;

    // ---- prologue: Q tile + first K tile in flight ----
    float4 pq[4], pk[4], pv[4];
    ldg_tile(Qb + (size_t)q0 * DKd, t, pq);
    ldg_tile(Kb, t, pk);
    sts_split(smc, OFF_QHI, OFF_QLO, t, pq, true);

    float sf[2][2] = {{0.f, 0.f}, {0.f, 0.f}};
    float sc[2][2] = {{0.f, 0.f}, {0.f, 0.f}};

    // ==================== PASS 1: denominators ====================
    for (int kt = 0; kt < Sq / TQt; kt++) {
        sts_split(smc, OFF_KHI, OFF_KLO, t, pk, false);   // hi plane only
        if (kt < Sq / TQt - 1) ldg_tile(Kb + (size_t)(kt + 1) * TQt * DKd, t, pk);
        __syncthreads();

        const bool two_term = (kt <= qt);
        float c[2][4][4];
        #pragma unroll
        for (int mi = 0; mi < 2; mi++)
            #pragma unroll
            for (int ni = 0; ni < 4; ni++)
                #pragma unroll
                for (int e = 0; e < 4; e++) c[mi][ni][e] = 0.f;

        #pragma unroll
        for (int ks = 0; ks < 4; ks++) {
            int kc = ks * 16;
            uint32_t qh[2][4], ql[2][4], bhf[2][4];
            #pragma unroll
            for (int mi = 0; mi < 2; mi++) {
                int r0 = mw * 32 + mi * 16 + aRow;
                ldm4(qh[mi], smb + OFF_QHI + r0 * SB + (kc + aCol) * 2);
                if (two_term)
                    ldm4(ql[mi], smb + OFF_QLO + r0 * SB + (kc + aCol) * 2);
            }
            #pragma unroll
            for (int p = 0; p < 2; p++) {
                int n0 = nw * 32 + p * 16 + bRow;
                ldm4(bhf[p], smb + OFF_KHI + n0 * SB + (kc + bCol) * 2);
            }
            #pragma unroll
            for (int mi = 0; mi < 2; mi++)
                #pragma unroll
                for (int ni = 0; ni < 4; ni++) {
                    const uint32_t* bb = &bhf[ni >> 1][(ni & 1) * 2];
                    MMAH(c[mi][ni], qh[mi], bb);
                    if (two_term) MMAH(c[mi][ni], ql[mi], bb);
                }
        }

        #pragma unroll
        for (int mi = 0; mi < 2; mi++) {
            int rg = q0 + mw * 32 + mi * 16 + g;
            #pragma unroll
            for (int ni = 0; ni < 4; ni++) {
                int cl = kt * TQt + nw * 32 + ni * 8 + 2 * tg;
                float e0 = __expf(c[mi][ni][0] * 0.125f);
                float e1 = __expf(c[mi][ni][1] * 0.125f);
                float e2 = __expf(c[mi][ni][2] * 0.125f);
                float e3 = __expf(c[mi][ni][3] * 0.125f);
                sf[mi][0] += e0 + e1;
                sf[mi][1] += e2 + e3;
                if (kt < qt) {
                    sc[mi][0] += e0 + e1;
                    sc[mi][1] += e2 + e3;
                } else if (kt == qt) {
                    if (cl     <= rg) sc[mi][0] += e0;
                    if (cl + 1 <= rg) sc[mi][0] += e1;
                    if (cl     <= rg + 8) sc[mi][1] += e2;
                    if (cl + 1 <= rg + 8) sc[mi][1] += e3;
                }
            }
        }
        __syncthreads();
    }

    // ---- reduce denominators: lanes (tg) then warps (nw) ----
    {
        float* redf = (float*)(smc + OFF_REDF);
        float* redc = (float*)(smc + OFF_REDC);
        #pragma unroll
        for (int mi = 0; mi < 2; mi++)
            #pragma unroll
            for (int rr = 0; rr < 2; rr++) {
                float vf = sf[mi][rr], vc = sc[mi][rr];
                vf += __shfl_xor_sync(0xffffffffu, vf, 1);
                vf += __shfl_xor_sync(0xffffffffu, vf, 2);
                vc += __shfl_xor_sync(0xffffffffu, vc, 1);
                vc += __shfl_xor_sync(0xffffffffu, vc, 2);
                if (tg == 0) {
                    int row = mw * 32 + mi * 16 + rr * 8 + g;
                    redf[row * 4 + nw] = vf;
                    redc[row * 4 + nw] = vc;
                }
            }
    }
    __syncthreads();
    if (t < 128) {
        const float* rf = (const float*)(smc + OFF_REDF) + t * 4;
        const float* rc = (const float*)(smc + OFF_REDC) + t * 4;
        float vf = (rf[0] + rf[1]) + (rf[2] + rf[3]);
        float vc = (rc[0] + rc[1]) + (rc[2] + rc[3]);
        ((float*)(smc + OFF_INV))[t] = 1.0f / (vc + 1e-8f * vf);
    }
    // zero-fill attn above diagonal tiles
    {
        int zc0 = (qt + 1) * TQt;
        int zf4 = (Sq - zc0) >> 2;
        if (zf4 > 0) {
            float4 z = make_float4(0.f, 0.f, 0.f, 0.f);
            for (int idx = t; idx < TQt * zf4; idx += NTHR) {
                int rr = idx / zf4, c4 = idx - rr * zf4;
                *(float4*)(attn_q + (size_t)rr * Sq + zc0 + c4 * 4) = z;
            }
        }
    }
    ldg_tile(Kb, t, pk);
    ldg_tile(Vb, t, pv);
    __syncthreads();

    float invr[2][2];
    #pragma unroll
    for (int mi = 0; mi < 2; mi++) {
        invr[mi][0] = ((const float*)(smc + OFF_INV))[mw * 32 + mi * 16 + g];
        invr[mi][1] = ((const float*)(smc + OFF_INV))[mw * 32 + mi * 16 + g + 8];
    }

    // ==================== PASS 2: attn + context ====================
    float av[2][2][4];
    #pragma unroll
    for (int mi = 0; mi < 2; mi++)
        #pragma unroll
        for (int ni = 0; ni < 2; ni++)
            #pragma unroll
            for (int e = 0; e < 4; e++) av[mi][ni][e] = 0.f;

    for (int kt = 0; kt <= qt; kt++) {
        sts_split(smc, OFF_KHI, OFF_KLO, t, pk, true);
        sts_split(smc, OFF_VHI, OFF_VLO, t, pv, true);
        __syncthreads();

        float c[2][4][4];
        #pragma unroll
        for (int mi = 0; mi < 2; mi++)
            #pragma unroll
            for (int ni = 0; ni < 4; ni++)
                #pragma unroll
                for (int e = 0; e < 4; e++) c[mi][ni][e] = 0.f;

        #pragma unroll
        for (int ks = 0; ks < 4; ks++) {
            int kc = ks * 16;
            uint32_t qh[2][4], ql[2][4], bhf[2][4], blf[2][4];
            #pragma unroll
            for (int mi = 0; mi < 2; mi++) {
                int r0 = mw * 32 + mi * 16 + aRow;
                ldm4(qh[mi], smb + OFF_QHI + r0 * SB + (kc + aCol) * 2);
                ldm4(ql[mi], smb + OFF_QLO + r0 * SB + (kc + aCol) * 2);
            }
            #pragma unroll
            for (int p = 0; p < 2; p++) {
                int n0 = nw * 32 + p * 16 + bRow;
                ldm4(bhf[p], smb + OFF_KHI + n0 * SB + (kc + bCol) * 2);
                ldm4(blf[p], smb + OFF_KLO + n0 * SB + (kc + bCol) * 2);
            }
            #pragma unroll
            for (int mi = 0; mi < 2; mi++)
                #pragma unroll
                for (int ni = 0; ni < 4; ni++) {
                    const uint32_t* bb = &bhf[ni >> 1][(ni & 1) * 2];
                    const uint32_t* bl = &blf[ni >> 1][(ni & 1) * 2];
                    MMAH(c[mi][ni], qh[mi], bb);
                    MMAH(c[mi][ni], qh[mi], bl);
                    MMAH(c[mi][ni], ql[mi], bb);
                }
        }

        if (kt < qt) {
            ldg_tile(Kb + (size_t)(kt + 1) * TQt * DKd, t, pk);
            ldg_tile(Vb + (size_t)(kt + 1) * TQt * DKd, t, pv);
        }

        // P = exp*inv (masked on diagonal tile): attn gmem + P fp16 smem
        const bool diag = (kt == qt);
        #pragma unroll
        for (int mi = 0; mi < 2; mi++) {
            int rloc0 = mw * 32 + mi * 16 + g;
            int rg = q0 + rloc0;
            #pragma unroll
            for (int ni = 0; ni < 4; ni++) {
                int cl = nw * 32 + ni * 8 + 2 * tg;
                int cg = kt * TQt + cl;
                float p0 = __expf(c[mi][ni][0] * 0.125f) * invr[mi][0];
                float p1 = __expf(c[mi][ni][1] * 0.125f) * invr[mi][0];
                float p2 = __expf(c[mi][ni][2] * 0.125f) * invr[mi][1];
                float p3 = __expf(c[mi][ni][3] * 0.125f) * invr[mi][1];
                if (diag) {
                    p0 = (cg     <= rg) ? p0 : 0.f;
                    p1 = (cg + 1 <= rg) ? p1 : 0.f;
                    p2 = (cg     <= rg + 8) ? p2 : 0.f;
                    p3 = (cg + 1 <= rg + 8) ? p3 : 0.f;
                }
                *(float2*)(attn_q + (size_t)rloc0 * Sq + cg)       = make_float2(p0, p1);
                *(float2*)(attn_q + (size_t)(rloc0 + 8) * Sq + cg) = make_float2(p2, p3);
                *(uint32_t*)(smc + OFF_P + rloc0 * SPB + cl * 2)       = packh(p0, p1);
                *(uint32_t*)(smc + OFF_P + (rloc0 + 8) * SPB + cl * 2) = packh(p2, p3);
            }
        }
        __syncthreads();

        // context += P @ V (2-term: P*Vhi + P*Vlo)
        #pragma unroll
        for (int ks = 0; ks < 8; ks++) {
            int kc = ks * 16;
            uint32_t ap[2][4];
            #pragma unroll
            for (int mi = 0; mi < 2; mi++) {
                int r0 = mw * 32 + mi * 16 + aRow;
                ldm4(ap[mi], smb + OFF_P + r0 * SPB + (kc + aCol) * 2);
            }
            #pragma unroll
            for (int ni = 0; ni < 2; ni++) {
                int dv0 = nw * 16 + ni * 8;
                uint32_t bhv[2], blv[2];
                ldm2t(bhv[0], bhv[1], smb + OFF_VHI + (kc + vRow) * SB + dv0 * 2);
                ldm2t(blv[0], blv[1], smb + OFF_VLO + (kc + vRow) * SB + dv0 * 2);
                #pragma unroll
                for (int mi = 0; mi < 2; mi++) {
                    MMAH(av[mi][ni], ap[mi], bhv);
                    MMAH(av[mi][ni], ap[mi], blv);
                }
            }
        }
        __syncthreads();
    }

    // ==================== context output ====================
    #pragma unroll
    for (int mi = 0; mi < 2; mi++) {
        int rloc0 = mw * 32 + mi * 16 + g;
        #pragma unroll
        for (int ni = 0; ni < 2; ni++) {
            int cl = nw * 16 + ni * 8 + 2 * tg;
            *(float2*)(out_ctx + ((size_t)bh * Sq + q0 + rloc0) * DKd + cl) =
                make_float2(av[mi][ni][0], av[mi][ni][1]);
            *(float2*)(out_ctx + ((size_t)bh * Sq + q0 + rloc0 + 8) * DKd + cl) =
                make_float2(av[mi][ni][2], av[mi][ni][3]);
        }
    }
}

extern "C" void kernel_launch(void* const* d_in, const int* in_sizes, int n_in,
                              void* d_out, int out_size)
{
    const float* Q = (const float*)d_in[0];
    const float* K = (const float*)d_in[1];
    const float* V = (const float*)d_in[2];
    float* ctx  = (float*)d_out;
    float* attn = (float*)d_out + (size_t)NBH * Sq * DKd;

    cudaFuncSetAttribute(sdpa_mma_kernel, cudaFuncAttributeMaxDynamicSharedMemorySize, SMEM_BYTES);
    dim3 grid(Sq / TQt, NBH);
    sdpa_mma_kernel<<<grid, NTHR, SMEM_BYTES>>>(Q, K, V, ctx, attn);
    (void)in_sizes; (void)n_in; (void)out_size;
}